// round 15
// baseline (speedup 1.0000x reference)
#include <cuda_runtime.h>
#include <cuda_bf16.h>
#include <math.h>

#define VOCAB  128000
#define NROWS  256
#define CSPLIT 16
#define SLICE  (VOCAB / CSPLIT)     /* 8000 */
#define S4     (SLICE / 4)          /* 2000 float4 */
#define T      256
#define ITERS  ((S4 + T - 1) / T)   /* 8 */
#define NB1    32                   /* coarse logit bins over [-3, 5] */
#define CAND   16384
#define KEYS   2048
#define BUCK   4096

typedef unsigned long long ull;

// ---------------- device-global scratch (static zero-init; self-resetting) ---
__device__ ull    g_pmax[NROWS][CSPLIT];
__device__ float  g_hist32[NROWS][CSPLIT][NB1];
__device__ double g_Zs[NROWS][CSPLIT];
__device__ int    g_tickA[NROWS];
__device__ int    g_tickB[NROWS];
__device__ float  g_invt[NROWS], g_negxm[NROWS];
__device__ int    g_c1[NROWS];
__device__ double g_cd[NROWS];
__device__ int    g_greedy[NROWS];
__device__ double g_zhi[NROWS];
__device__ int    g_nkept[NROWS];
__device__ int    g_cnt[NROWS];
__device__ ull    g_cand[NROWS][CAND];    /* 33.5MB */
__device__ ull    g_best[NROWS];

// ---------------- helpers ----------------------------------------------------
__device__ __forceinline__ float comp_e(float l, float invt, float negxm) {
    return __expf(__fmaf_rn(l, invt, negxm));
}
__device__ __forceinline__ unsigned ordbits(float f) {
    unsigned u = __float_as_uint(f);
    return (u & 0x80000000u) ? ~u : (u | 0x80000000u);
}
__device__ __forceinline__ float unordbits(unsigned u) {
    unsigned b = (u & 0x80000000u) ? (u & 0x7FFFFFFFu) : ~u;
    return __uint_as_float(b);
}
// coarse bin: 32 bins of width 0.25 over l in [-3, 5]; pure function of l,
// identical expression in kA and kB (bitwise-consistent classification)
__device__ __forceinline__ int lbin32(float l) {
    int b = __float2int_rd(__fmaf_rn(l, 4.0f, 12.0f));
    return min(NB1 - 1, max(0, b));
}
// JAX threefry2x32, 20 rounds, key = (0, 1)
__device__ __forceinline__ void threefry01(unsigned& x0, unsigned& x1) {
    const unsigned k0 = 0u, k1 = 1u, k2 = 0x1BD11BDAu ^ k0 ^ k1;
    x0 += k0; x1 += k1;
#define TFR(r) { x0 += x1; x1 = __funnelshift_l(x1, x1, (r)); x1 ^= x0; }
    TFR(13) TFR(15) TFR(26) TFR(6)
    x0 += k1; x1 += k2 + 1u;
    TFR(17) TFR(29) TFR(16) TFR(24)
    x0 += k2; x1 += k0 + 2u;
    TFR(13) TFR(15) TFR(26) TFR(6)
    x0 += k0; x1 += k1 + 3u;
    TFR(17) TFR(29) TFR(16) TFR(24)
    x0 += k1; x1 += k2 + 4u;
    TFR(13) TFR(15) TFR(26) TFR(6)
    x0 += k2; x1 += k0 + 5u;
#undef TFR
}
__device__ __forceinline__ ull race_pack(float e, int row, int v) {
    unsigned x0 = 0u;
    unsigned x1 = (unsigned)row * (unsigned)VOCAB + (unsigned)v;
    threefry01(x0, x1);
    unsigned bits = x0 ^ x1;
    float u  = __uint_as_float((bits >> 9) | 0x3F800000u) - 1.0f;
    float nz = fmaxf(-log1pf(-u), 1e-10f);
    float sc = __fdividef(e, nz);
    return ((ull)__float_as_uint(sc) << 32) | (ull)(unsigned)(~(unsigned)v);
}

// =============================================================================
// K_A: max/argmax + Z (Kahan) + conflict-free 32-bin coarse mass histogram;
//      last CTA per row: double rescale/reduce + coarse scan -> c1, cd, params.
// =============================================================================
__global__ __launch_bounds__(T) void kA(const float* __restrict__ logits,
                                        const float* __restrict__ temps,
                                        const float* __restrict__ topps)
{
    __shared__ float  hA[NB1 * 256];    // 32KB: [bin][warp*32+lane], bank=lane
    __shared__ ull    sr[T];
    __shared__ double sd[T];
    __shared__ double s_scale[CSPLIT];
    __shared__ int    s_last;

    const int row = blockIdx.y, c = blockIdx.x, tid = threadIdx.x;
    const float4* L4 = reinterpret_cast<const float4*>(
        logits + (size_t)row * VOCAB + (size_t)c * SLICE);

    // ---- pass A: slice max + argmax ----------------------------------------
    float bm = -INFINITY; int bi = 0;
    for (int i = tid; i < S4; i += T) {
        float4 qv = L4[i]; int b = c * SLICE + 4 * i;
        if (qv.x > bm) { bm = qv.x; bi = b; }
        if (qv.y > bm) { bm = qv.y; bi = b + 1; }
        if (qv.z > bm) { bm = qv.z; bi = b + 2; }
        if (qv.w > bm) { bm = qv.w; bi = b + 3; }
    }
    sr[tid] = ((ull)ordbits(bm) << 32) | (ull)(unsigned)(~(unsigned)bi);
    __syncthreads();
    for (int o = T >> 1; o > 0; o >>= 1) {
        if (tid < o && sr[tid + o] > sr[tid]) sr[tid] = sr[tid + o];
        __syncthreads();
    }
    const ull pm = sr[0];
    if (tid == 0) g_pmax[row][c] = pm;

    for (int i = tid; i < NB1 * 256; i += T) hA[i] = 0.0f;
    __syncthreads();

    const float temp  = temps[row];
    const float t     = fmaxf(temp, 1e-5f);
    const float invt  = __frcp_rn(t);
    const float mc    = unordbits((unsigned)(pm >> 32));
    const float negxc = -__fmul_rn(mc, invt);

    // ---- pass B (slice L1-hot): Z (Kahan) + conflict-free coarse hist ------
    float zs = 0.0f, zc = 0.0f;
    for (int i = tid; i < S4; i += T) {
        float4 qv = L4[i];
        float ls[4] = { qv.x, qv.y, qv.z, qv.w };
        #pragma unroll
        for (int j = 0; j < 4; j++) {
            float l = ls[j];
            float e = comp_e(l, invt, negxc);
            float y = e - zc; float t2 = zs + y; zc = (t2 - zs) - y; zs = t2;
            hA[(lbin32(l) << 8) + tid] += e;   // LDS/FADD/STS, bank = lane
        }
    }
    sd[tid] = (double)zs - (double)zc;
    __syncthreads();
    for (int o = T >> 1; o > 0; o >>= 1) {
        if (tid < o) sd[tid] += sd[tid + o];
        __syncthreads();
    }
    if (tid == 0) g_Zs[row][c] = sd[0];
    // fold 256 copies per bin (8 threads per bin, shfl-free strided partials)
    if (tid < NB1 * 8) {
        int b = tid >> 3, s0 = (tid & 7) << 5;
        float v = 0.0f;
        #pragma unroll
        for (int s = 0; s < 32; s++) v += hA[(b << 8) + s0 + s];
        hA[(b << 8) + s0] = v;
    }
    __syncthreads();
    if (tid < NB1) {
        float v = 0.0f;
        #pragma unroll
        for (int s = 0; s < 8; s++) v += hA[(tid << 8) + (s << 5)];
        g_hist32[row][c][tid] = v;
    }
    __threadfence();
    __syncthreads();
    if (tid == 0) s_last = (atomicAdd(&g_tickA[row], 1) == CSPLIT - 1);
    __syncthreads();
    if (!s_last) return;
    __threadfence();

    // ---- last CTA of row: rescale, reduce, coarse suffix scan --------------
    if (tid == 0) g_tickA[row] = 0;
    ull k = g_pmax[row][0];
    #pragma unroll
    for (int j = 1; j < CSPLIT; j++) { ull o = g_pmax[row][j]; if (o > k) k = o; }
    const float m = unordbits((unsigned)(k >> 32));
    if (tid < CSPLIT) {
        float mcj = unordbits((unsigned)(g_pmax[row][tid] >> 32));
        s_scale[tid] = exp(((double)mcj - (double)m) * (double)invt);
    }
    __syncthreads();
    if (tid < NB1) {
        double v = 0.0;
        #pragma unroll
        for (int cs = 0; cs < CSPLIT; cs++)
            v += s_scale[cs] * (double)g_hist32[row][cs][tid];
        sd[tid] = v;
    }
    __syncthreads();
    if (tid == 0) {
        double Z = 0.0;
        #pragma unroll
        for (int cs = 0; cs < CSPLIT; cs++) Z += s_scale[cs] * g_Zs[row][cs];
        double cd = (double)topps[row] * Z;
        double cum = 0.0; int c1 = 0;
        for (int b = NB1 - 1; b >= 0; b--) {
            cum += sd[b];
            if (cum > cd) { c1 = b; break; }
        }
        g_c1[row]    = c1;
        g_cd[row]    = cd;
        g_invt[row]  = invt;
        g_negxm[row] = -__fmul_rn(m, invt);
        g_greedy[row] = (int)(~(unsigned)(k & 0xFFFFFFFFull));
        g_cnt[row] = 0; g_best[row] = 0ull; g_zhi[row] = 0.0; g_nkept[row] = 0;
    }
}

// =============================================================================
// K_B: bin-compare classification, warp-compacted race (exp in drain),
//      candidate gather; last CTA: exact mini-pipeline over <=16K candidates.
// =============================================================================
__global__ __launch_bounds__(T) void kB(const float* __restrict__ logits,
                                        const float* __restrict__ temps,
                                        float* __restrict__ out)
{
    __shared__ ull    sr[T];
    __shared__ double sd[T];
    __shared__ int    si[T];
    __shared__ uint2  q[8][64];        // 4KB per-warp kept-token queues
    __shared__ ull    keysB[KEYS];     // 16KB
    __shared__ float  bmass[BUCK];     // 16KB
    __shared__ int    s_last, s_r2, s_m2, s_K;
    __shared__ double s_z2;
    __shared__ int    s_na;
    __shared__ ull    s_bA;

    const int row = blockIdx.y, c = blockIdx.x, tid = threadIdx.x;
    const int wid = tid >> 5, lane = tid & 31;
    const unsigned lmlt = (1u << lane) - 1u;
    const int   c1 = g_c1[row];
    const float invt = g_invt[row], negxm = g_negxm[row];
    const float4* L4 = reinterpret_cast<const float4*>(
        logits + (size_t)row * VOCAB + (size_t)c * SLICE);

    ull best = 0ull; float zs = 0.0f, zc = 0.0f; int qn = 0, nk = 0;
    for (int it = 0; it < ITERS; it++) {
        int i = tid + it * T;
        bool valid = i < S4;
        float4 qv = valid ? L4[i] : make_float4(-1e30f, -1e30f, -1e30f, -1e30f);
        float ls[4] = { qv.x, qv.y, qv.z, qv.w };
        int vb = c * SLICE + 4 * i;
        #pragma unroll
        for (int j = 0; j < 4; j++) {
            float l = ls[j];
            int b = lbin32(l);
            bool kept = valid && (b > c1);
            unsigned bal = __ballot_sync(0xFFFFFFFFu, kept);
            if (kept) {
                int pos = qn + __popc(bal & lmlt);
                q[wid][pos] = make_uint2(__float_as_uint(l), (unsigned)(vb + j));
            }
            qn += __popc(bal); nk += __popc(bal);
            if (qn >= 32) {                 // warp-uniform
                qn -= 32;
                uint2 en = q[wid][qn + lane];
                float e = comp_e(__uint_as_float(en.x), invt, negxm);
                float y = e - zc; float t2 = zs + y; zc = (t2 - zs) - y; zs = t2;
                ull pk = race_pack(e, row, (int)en.y);
                if (pk > best) best = pk;
            }
            if (valid && (b == c1)) {
                float e = comp_e(l, invt, negxm);
                unsigned eb = __float_as_uint(e);
                if (eb != 0u) {
                    int p = atomicAdd(&g_cnt[row], 1);
                    if (p < CAND)
                        g_cand[row][p] = ((ull)(~eb) << 32) | (ull)(unsigned)(vb + j);
                }
            }
        }
    }
    if (lane < qn) {                        // drain leftovers
        uint2 en = q[wid][lane];
        float e = comp_e(__uint_as_float(en.x), invt, negxm);
        float y = e - zc; float t2 = zs + y; zc = (t2 - zs) - y; zs = t2;
        ull pk = race_pack(e, row, (int)en.y);
        if (pk > best) best = pk;
    }
    sr[tid] = best;
    sd[tid] = (double)zs - (double)zc;
    si[tid] = (lane == 0) ? nk : 0;         // nk warp-uniform
    __syncthreads();
    for (int o = T >> 1; o > 0; o >>= 1) {
        if (tid < o) {
            if (sr[tid + o] > sr[tid]) sr[tid] = sr[tid + o];
            sd[tid] += sd[tid + o];
            si[tid] += si[tid + o];
        }
        __syncthreads();
    }
    if (tid == 0) {
        if (sr[0]) atomicMax(&g_best[row], sr[0]);
        atomicAdd(&g_zhi[row], sd[0]);
        atomicAdd(&g_nkept[row], si[0]);
    }
    __threadfence();
    __syncthreads();
    if (tid == 0) s_last = (atomicAdd(&g_tickB[row], 1) == CSPLIT - 1);
    __syncthreads();
    if (!s_last) return;
    __threadfence();

    // ================== last CTA: exact mini-pipeline ========================
    if (tid == 0) {
        g_tickB[row] = 0;
        s_r2 = 0x7FFFFFFF; s_m2 = 0; s_K = -1;
    }
    const int    cnt   = g_cnt[row];
    const int    n     = min(cnt, CAND);
    const double cd    = g_cd[row];
    const double zsure = g_zhi[row];
    const int    nkept = g_nkept[row];
    const ull    gbest = g_best[row];
    for (int i = tid; i < BUCK; i += T) bmass[i] = 0.0f;
    __syncthreads();

    // bucket masses over candidate e-bits (<=16K smem atomics total: cheap)
    for (int i = tid; i < n; i += T) {
        unsigned eb = ~(unsigned)(g_cand[row][i] >> 32);
        atomicAdd(&bmass[eb >> 18], __uint_as_float(eb));
    }
    __syncthreads();
    // suffix scan (desc) vs remaining budget
    {
        double loc[16]; double part = 0.0;
        #pragma unroll
        for (int j = 0; j < 16; j++) {
            int r = tid * 16 + j;
            part += (double)bmass[BUCK - 1 - r];
            loc[j] = part;
        }
        sd[tid] = part;
        __syncthreads();
        for (int off = 1; off < T; off <<= 1) {
            double add = (tid >= off) ? sd[tid - off] : 0.0;
            __syncthreads();
            sd[tid] += add;
            __syncthreads();
        }
        const double budget = cd - zsure;
        double base = (tid > 0) ? sd[tid - 1] : 0.0;
        #pragma unroll
        for (int j = 0; j < 16; j++) {
            if (base + loc[j] > budget) { atomicMin(&s_r2, tid * 16 + j); break; }
        }
    }
    __syncthreads();
    const int b2 = (s_r2 == 0x7FFFFFFF) ? -1 : (BUCK - 1 - s_r2);

    // exact above-mass + race above-bucket candidates + gather crossing bucket
    double z2 = 0.0; int na = 0; ull bA = 0ull;
    for (int i = tid; i < n; i += T) {
        ull key = g_cand[row][i];
        unsigned eb = ~(unsigned)(key >> 32);
        int bu = (int)(eb >> 18);
        if (bu > b2) {
            z2 += (double)__uint_as_float(eb);
            na++;
            ull pk = race_pack(__uint_as_float(eb), row,
                               (int)(unsigned)(key & 0xFFFFFFFFull));
            if (pk > bA) bA = pk;
        } else if (bu == b2) {
            int p = atomicAdd(&s_m2, 1);
            if (p < KEYS) keysB[p] = key;
        }
    }
    sr[tid] = bA; sd[tid] = z2; si[tid] = na;
    __syncthreads();
    for (int o = T >> 1; o > 0; o >>= 1) {
        if (tid < o) {
            if (sr[tid + o] > sr[tid]) sr[tid] = sr[tid + o];
            sd[tid] += sd[tid + o];
            si[tid] += si[tid + o];
        }
        __syncthreads();
    }
    if (tid == 0) { s_bA = sr[0]; s_z2 = sd[0]; s_na = si[0]; }
    __syncthreads();

    const int m2full = s_m2;
    const int m2 = min(m2full, KEYS);
    int msz = 32; while (msz < m2) msz <<= 1;
    for (int i = tid; i < msz; i += T)
        if (i >= m2) keysB[i] = 0xFFFFFFFFFFFFFFFFull;
    __syncthreads();
    if (m2 > 0) {
        for (int kk = 2; kk <= msz; kk <<= 1) {
            for (int jj = kk >> 1; jj > 0; jj >>= 1) {
                for (int i2 = tid; i2 < msz; i2 += T) {
                    int ixj = i2 ^ jj;
                    if (ixj > i2) {
                        ull a = keysB[i2], b = keysB[ixj];
                        bool up = ((i2 & kk) == 0);
                        if ((a > b) == up) { keysB[i2] = b; keysB[ixj] = a; }
                    }
                }
                __syncthreads();
            }
        }
    }
    // parallel exact prefix scan over sorted crossing bucket -> K
    {
        double loc[8]; double part = 0.0;
        #pragma unroll
        for (int j = 0; j < 8; j++) {
            int idx = tid * 8 + j;
            double ev = (idx < m2)
                ? (double)__uint_as_float(~(unsigned)(keysB[idx] >> 32)) : 0.0;
            part += ev; loc[j] = part;
        }
        sd[tid] = part;
        __syncthreads();
        for (int off = 1; off < T; off <<= 1) {
            double add = (tid >= off) ? sd[tid - off] : 0.0;
            __syncthreads();
            sd[tid] += add;
            __syncthreads();
        }
        const double cum0 = zsure + s_z2;
        double base = (tid > 0) ? sd[tid - 1] : 0.0;
        #pragma unroll
        for (int j = 0; j < 8; j++) {
            int idx = tid * 8 + j;
            if (idx < m2 && (cum0 + base + loc[j]) <= cd) atomicMax(&s_K, idx);
        }
    }
    __syncthreads();
    int K = s_K;
    if (m2full > KEYS || cnt > CAND) K = m2 - 1;           // overflow fallback
    if (K < 0 && nkept == 0 && s_na == 0 && m2 > 0) K = 0; // rank 0 always kept

    ull b3 = (tid == 0) ? (gbest > s_bA ? gbest : s_bA) : 0ull;
    for (int i = tid; i <= K; i += T) {
        ull key = keysB[i];
        unsigned eb = ~(unsigned)(key >> 32);
        ull pk = race_pack(__uint_as_float(eb), row,
                           (int)(unsigned)(key & 0xFFFFFFFFull));
        if (pk > b3) b3 = pk;
    }
    sr[tid] = b3;
    __syncthreads();
    for (int o = T >> 1; o > 0; o >>= 1) {
        if (tid < o && sr[tid + o] > sr[tid]) sr[tid] = sr[tid + o];
        __syncthreads();
    }
    if (tid == 0) {
        int greedy = g_greedy[row];
        int winner = (sr[0] == 0ull) ? greedy
                                     : (int)(~(unsigned)(sr[0] & 0xFFFFFFFFull));
        float temp = temps[row];
        out[row] = (float)((temp <= 1e-10f) ? greedy : winner);
    }
}

extern "C" void kernel_launch(void* const* d_in, const int* in_sizes, int n_in,
                              void* d_out, int out_size) {
    const float* logits = (const float*)d_in[0];
    const float* temps  = (const float*)d_in[1];
    const float* topps  = (const float*)d_in[2];
    float* out = (float*)d_out;

    kA<<<dim3(CSPLIT, NROWS), T>>>(logits, temps, topps);
    kB<<<dim3(CSPLIT, NROWS), T>>>(logits, temps, out);
}

// round 16
// speedup vs baseline: 1.1997x; 1.1997x over previous
#include <cuda_runtime.h>
#include <cuda_bf16.h>
#include <math.h>

#define VOCAB  128000
#define NROWS  256
#define CSPLIT 16
#define SLICE  (VOCAB / CSPLIT)     /* 8000 */
#define S4     (SLICE / 4)          /* 2000 float4 */
#define T      256
#define ITERS  ((S4 + T - 1) / T)   /* 8 */
#define NB1    32                   /* coarse logit bins over [-3, 5] */
#define CAND   16384
#define KEYS   2048
#define BUCK   4096
#define BUFSZ  1024                 /* per-CTA smem candidate buffer */

typedef unsigned long long ull;

// ---------------- device-global scratch (static zero-init; self-resetting) ---
__device__ ull    g_pmax[NROWS][CSPLIT];
__device__ float  g_hist32[NROWS][CSPLIT][NB1];
__device__ double g_Zs[NROWS][CSPLIT];
__device__ int    g_tickA[NROWS];
__device__ float  g_invt[NROWS], g_negxm[NROWS];
__device__ int    g_c1[NROWS];
__device__ double g_cd[NROWS];
__device__ int    g_greedy[NROWS];
__device__ double g_zhi[NROWS];
__device__ int    g_nkept[NROWS];
__device__ int    g_cnt[NROWS];
__device__ ull    g_cand[NROWS][CAND];    /* 33.5MB */
__device__ ull    g_best[NROWS];

// ---------------- helpers ----------------------------------------------------
__device__ __forceinline__ float comp_e(float l, float invt, float negxm) {
    return __expf(__fmaf_rn(l, invt, negxm));
}
__device__ __forceinline__ unsigned ordbits(float f) {
    unsigned u = __float_as_uint(f);
    return (u & 0x80000000u) ? ~u : (u | 0x80000000u);
}
__device__ __forceinline__ float unordbits(unsigned u) {
    unsigned b = (u & 0x80000000u) ? (u & 0x7FFFFFFFu) : ~u;
    return __uint_as_float(b);
}
// coarse bin: 32 bins of width 0.25 over l in [-3, 5]; pure function of l
__device__ __forceinline__ int lbin32(float l) {
    int b = __float2int_rd(__fmaf_rn(l, 4.0f, 12.0f));
    return min(NB1 - 1, max(0, b));
}
// JAX threefry2x32, 20 rounds, key = (0, 1)
__device__ __forceinline__ void threefry01(unsigned& x0, unsigned& x1) {
    const unsigned k0 = 0u, k1 = 1u, k2 = 0x1BD11BDAu ^ k0 ^ k1;
    x0 += k0; x1 += k1;
#define TFR(r) { x0 += x1; x1 = __funnelshift_l(x1, x1, (r)); x1 ^= x0; }
    TFR(13) TFR(15) TFR(26) TFR(6)
    x0 += k1; x1 += k2 + 1u;
    TFR(17) TFR(29) TFR(16) TFR(24)
    x0 += k2; x1 += k0 + 2u;
    TFR(13) TFR(15) TFR(26) TFR(6)
    x0 += k0; x1 += k1 + 3u;
    TFR(17) TFR(29) TFR(16) TFR(24)
    x0 += k1; x1 += k2 + 4u;
    TFR(13) TFR(15) TFR(26) TFR(6)
    x0 += k2; x1 += k0 + 5u;
#undef TFR
}
__device__ __forceinline__ ull race_pack(float e, int row, int v) {
    unsigned x0 = 0u;
    unsigned x1 = (unsigned)row * (unsigned)VOCAB + (unsigned)v;
    threefry01(x0, x1);
    unsigned bits = x0 ^ x1;
    float u  = __uint_as_float((bits >> 9) | 0x3F800000u) - 1.0f;
    float nz = fmaxf(-log1pf(-u), 1e-10f);
    float sc = __fdividef(e, nz);
    return ((ull)__float_as_uint(sc) << 32) | (ull)(unsigned)(~(unsigned)v);
}

// =============================================================================
// K_A: max/argmax + Z (Kahan) + conflict-free 32-bin coarse mass histogram;
//      last CTA per row: double rescale/reduce + coarse scan -> c1, cd, params.
// (unchanged from R15 — measured ~83us)
// =============================================================================
__global__ __launch_bounds__(T) void kA(const float* __restrict__ logits,
                                        const float* __restrict__ temps,
                                        const float* __restrict__ topps)
{
    __shared__ float  hA[NB1 * 256];    // 32KB: [bin][slot=tid], bank = lane
    __shared__ ull    sr[T];
    __shared__ double sd[T];
    __shared__ double s_scale[CSPLIT];
    __shared__ int    s_last;

    const int row = blockIdx.y, c = blockIdx.x, tid = threadIdx.x;
    const float4* L4 = reinterpret_cast<const float4*>(
        logits + (size_t)row * VOCAB + (size_t)c * SLICE);

    float bm = -INFINITY; int bi = 0;
    for (int i = tid; i < S4; i += T) {
        float4 qv = L4[i]; int b = c * SLICE + 4 * i;
        if (qv.x > bm) { bm = qv.x; bi = b; }
        if (qv.y > bm) { bm = qv.y; bi = b + 1; }
        if (qv.z > bm) { bm = qv.z; bi = b + 2; }
        if (qv.w > bm) { bm = qv.w; bi = b + 3; }
    }
    sr[tid] = ((ull)ordbits(bm) << 32) | (ull)(unsigned)(~(unsigned)bi);
    __syncthreads();
    for (int o = T >> 1; o > 0; o >>= 1) {
        if (tid < o && sr[tid + o] > sr[tid]) sr[tid] = sr[tid + o];
        __syncthreads();
    }
    const ull pm = sr[0];
    if (tid == 0) g_pmax[row][c] = pm;

    for (int i = tid; i < NB1 * 256; i += T) hA[i] = 0.0f;
    __syncthreads();

    const float temp  = temps[row];
    const float t     = fmaxf(temp, 1e-5f);
    const float invt  = __frcp_rn(t);
    const float mc    = unordbits((unsigned)(pm >> 32));
    const float negxc = -__fmul_rn(mc, invt);

    float zs = 0.0f, zc = 0.0f;
    for (int i = tid; i < S4; i += T) {
        float4 qv = L4[i];
        float ls[4] = { qv.x, qv.y, qv.z, qv.w };
        #pragma unroll
        for (int j = 0; j < 4; j++) {
            float l = ls[j];
            float e = comp_e(l, invt, negxc);
            float y = e - zc; float t2 = zs + y; zc = (t2 - zs) - y; zs = t2;
            hA[(lbin32(l) << 8) + tid] += e;
        }
    }
    sd[tid] = (double)zs - (double)zc;
    __syncthreads();
    for (int o = T >> 1; o > 0; o >>= 1) {
        if (tid < o) sd[tid] += sd[tid + o];
        __syncthreads();
    }
    if (tid == 0) g_Zs[row][c] = sd[0];
    if (tid < NB1 * 8) {
        int b = tid >> 3, s0 = (tid & 7) << 5;
        float v = 0.0f;
        #pragma unroll
        for (int s = 0; s < 32; s++) v += hA[(b << 8) + s0 + s];
        hA[(b << 8) + s0] = v;
    }
    __syncthreads();
    if (tid < NB1) {
        float v = 0.0f;
        #pragma unroll
        for (int s = 0; s < 8; s++) v += hA[(tid << 8) + (s << 5)];
        g_hist32[row][c][tid] = v;
    }
    __threadfence();
    __syncthreads();
    if (tid == 0) s_last = (atomicAdd(&g_tickA[row], 1) == CSPLIT - 1);
    __syncthreads();
    if (!s_last) return;
    __threadfence();

    if (tid == 0) g_tickA[row] = 0;
    ull k = g_pmax[row][0];
    #pragma unroll
    for (int j = 1; j < CSPLIT; j++) { ull o = g_pmax[row][j]; if (o > k) k = o; }
    const float m = unordbits((unsigned)(k >> 32));
    if (tid < CSPLIT) {
        float mcj = unordbits((unsigned)(g_pmax[row][tid] >> 32));
        s_scale[tid] = exp(((double)mcj - (double)m) * (double)invt);
    }
    __syncthreads();
    if (tid < NB1) {
        double v = 0.0;
        #pragma unroll
        for (int cs = 0; cs < CSPLIT; cs++)
            v += s_scale[cs] * (double)g_hist32[row][cs][tid];
        sd[tid] = v;
    }
    __syncthreads();
    if (tid == 0) {
        double Z = 0.0;
        #pragma unroll
        for (int cs = 0; cs < CSPLIT; cs++) Z += s_scale[cs] * g_Zs[row][cs];
        double cd = (double)topps[row] * Z;
        double cum = 0.0; int c1 = 0;
        for (int b = NB1 - 1; b >= 0; b--) {
            cum += sd[b];
            if (cum > cd) { c1 = b; break; }
        }
        g_c1[row]    = c1;
        g_cd[row]    = cd;
        g_invt[row]  = invt;
        g_negxm[row] = -__fmul_rn(m, invt);
        g_greedy[row] = (int)(~(unsigned)(k & 0xFFFFFFFFull));
        g_cnt[row] = 0; g_best[row] = 0ull; g_zhi[row] = 0.0; g_nkept[row] = 0;
    }
}

// =============================================================================
// K_B: bin-compare classification, warp-compacted race (exp in drain),
//      BUFFERED candidate gather (smem buffer + one flush per CTA).
// =============================================================================
__global__ __launch_bounds__(T) void kB(const float* __restrict__ logits)
{
    __shared__ ull    buf[BUFSZ];      // 8KB candidate buffer
    __shared__ ull    sr[T];
    __shared__ double sd[T];
    __shared__ int    si[T];
    __shared__ uint2  q[8][64];        // 4KB per-warp kept-token queues
    __shared__ int    s_bn, s_base;

    const int row = blockIdx.y, c = blockIdx.x, tid = threadIdx.x;
    const int wid = tid >> 5, lane = tid & 31;
    const unsigned lmlt = (1u << lane) - 1u;
    const int   c1 = g_c1[row];
    const float invt = g_invt[row], negxm = g_negxm[row];
    const float4* L4 = reinterpret_cast<const float4*>(
        logits + (size_t)row * VOCAB + (size_t)c * SLICE);

    if (tid == 0) s_bn = 0;
    __syncthreads();

    ull best = 0ull; float zs = 0.0f, zc = 0.0f; int qn = 0, nk = 0;
    for (int it = 0; it < ITERS; it++) {
        int i = tid + it * T;
        bool valid = i < S4;
        float4 qv = valid ? L4[i] : make_float4(-1e30f, -1e30f, -1e30f, -1e30f);
        float ls[4] = { qv.x, qv.y, qv.z, qv.w };
        int vb = c * SLICE + 4 * i;
        #pragma unroll
        for (int j = 0; j < 4; j++) {
            float l = ls[j];
            int b = lbin32(l);
            bool kept = valid && (b > c1);
            unsigned bal = __ballot_sync(0xFFFFFFFFu, kept);
            if (kept) {
                int pos = qn + __popc(bal & lmlt);
                q[wid][pos] = make_uint2(__float_as_uint(l), (unsigned)(vb + j));
            }
            qn += __popc(bal); nk += __popc(bal);
            if (qn >= 32) {                 // warp-uniform
                qn -= 32;
                uint2 en = q[wid][qn + lane];
                float e = comp_e(__uint_as_float(en.x), invt, negxm);
                float y = e - zc; float t2 = zs + y; zc = (t2 - zs) - y; zs = t2;
                ull pk = race_pack(e, row, (int)en.y);
                if (pk > best) best = pk;
            }
            // candidate: warp-aggregated smem buffer write
            bool cnd = valid && (b == c1);
            ull key = 0ull;
            if (cnd) {
                float e = comp_e(l, invt, negxm);
                unsigned eb = __float_as_uint(e);
                if (eb == 0u) cnd = false;
                else key = ((ull)(~eb) << 32) | (ull)(unsigned)(vb + j);
            }
            unsigned calb = __ballot_sync(0xFFFFFFFFu, cnd);
            if (calb) {
                int leader = __ffs(calb) - 1;
                int base = 0;
                if (lane == leader) base = atomicAdd(&s_bn, __popc(calb));
                base = __shfl_sync(0xFFFFFFFFu, base, leader);
                if (cnd) {
                    int p = base + __popc(calb & lmlt);
                    if (p < BUFSZ) buf[p] = key;
                    else {                       // rare spill
                        int gp = atomicAdd(&g_cnt[row], 1);
                        if (gp < CAND) g_cand[row][gp] = key;
                    }
                }
            }
        }
    }
    if (lane < qn) {                        // drain leftovers
        uint2 en = q[wid][lane];
        float e = comp_e(__uint_as_float(en.x), invt, negxm);
        float y = e - zc; float t2 = zs + y; zc = (t2 - zs) - y; zs = t2;
        ull pk = race_pack(e, row, (int)en.y);
        if (pk > best) best = pk;
    }
    sr[tid] = best;
    sd[tid] = (double)zs - (double)zc;
    si[tid] = (lane == 0) ? nk : 0;         // nk warp-uniform
    __syncthreads();
    for (int o = T >> 1; o > 0; o >>= 1) {
        if (tid < o) {
            if (sr[tid + o] > sr[tid]) sr[tid] = sr[tid + o];
            sd[tid] += sd[tid + o];
            si[tid] += si[tid + o];
        }
        __syncthreads();
    }
    // flush buffered candidates: one global atomic + coalesced copy
    const int bn = min(s_bn, BUFSZ);
    if (tid == 0) {
        s_base = (bn > 0) ? atomicAdd(&g_cnt[row], bn) : 0;
        if (sr[0]) atomicMax(&g_best[row], sr[0]);
        atomicAdd(&g_zhi[row], sd[0]);
        atomicAdd(&g_nkept[row], si[0]);
    }
    __syncthreads();
    const int base = s_base;
    for (int i = tid; i < bn; i += T) {
        int p = base + i;
        if (p < CAND) g_cand[row][p] = buf[i];
    }
}

// =============================================================================
// K_C: per-row exact mini-pipeline over <=16K candidates -> out[row]
// smem union: bmass (16KB floats) then keysB (16KB ull)
// =============================================================================
__global__ __launch_bounds__(T) void kC(const float* __restrict__ temps,
                                        float* __restrict__ out)
{
    __shared__ ull    s_un[KEYS];      // 16KB; aliased as float bmass[BUCK]
    __shared__ ull    sr[T];
    __shared__ double sd[T];
    __shared__ int    si[T];
    __shared__ int    s_r2, s_m2, s_K;
    __shared__ double s_z2;
    __shared__ int    s_na;
    __shared__ ull    s_bA;

    float* bmass = reinterpret_cast<float*>(s_un);
    ull*   keysB = s_un;

    const int row = blockIdx.x, tid = threadIdx.x;
    if (tid == 0) { s_r2 = 0x7FFFFFFF; s_m2 = 0; s_K = -1; }
    const int    cnt   = g_cnt[row];
    const int    n     = min(cnt, CAND);
    const double cd    = g_cd[row];
    const double zsure = g_zhi[row];
    const int    nkept = g_nkept[row];
    const ull    gbest = g_best[row];

    for (int i = tid; i < BUCK; i += T) bmass[i] = 0.0f;
    __syncthreads();
    for (int i = tid; i < n; i += T) {
        unsigned eb = ~(unsigned)(g_cand[row][i] >> 32);
        atomicAdd(&bmass[eb >> 18], __uint_as_float(eb));
    }
    __syncthreads();
    {
        double loc[16]; double part = 0.0;
        #pragma unroll
        for (int j = 0; j < 16; j++) {
            int r = tid * 16 + j;
            part += (double)bmass[BUCK - 1 - r];
            loc[j] = part;
        }
        sd[tid] = part;
        __syncthreads();
        for (int off = 1; off < T; off <<= 1) {
            double add = (tid >= off) ? sd[tid - off] : 0.0;
            __syncthreads();
            sd[tid] += add;
            __syncthreads();
        }
        const double budget = cd - zsure;
        double b0 = (tid > 0) ? sd[tid - 1] : 0.0;
        #pragma unroll
        for (int j = 0; j < 16; j++) {
            if (b0 + loc[j] > budget) { atomicMin(&s_r2, tid * 16 + j); break; }
        }
    }
    __syncthreads();
    const int b2 = (s_r2 == 0x7FFFFFFF) ? -1 : (BUCK - 1 - s_r2);
    __syncthreads();          // bmass reads done; keysB reuse safe after this

    double z2 = 0.0; int na = 0; ull bA = 0ull;
    for (int i = tid; i < n; i += T) {
        ull key = g_cand[row][i];
        unsigned eb = ~(unsigned)(key >> 32);
        int bu = (int)(eb >> 18);
        if (bu > b2) {
            z2 += (double)__uint_as_float(eb);
            na++;
            ull pk = race_pack(__uint_as_float(eb), row,
                               (int)(unsigned)(key & 0xFFFFFFFFull));
            if (pk > bA) bA = pk;
        } else if (bu == b2) {
            int p = atomicAdd(&s_m2, 1);
            if (p < KEYS) keysB[p] = key;
        }
    }
    sr[tid] = bA; sd[tid] = z2; si[tid] = na;
    __syncthreads();
    for (int o = T >> 1; o > 0; o >>= 1) {
        if (tid < o) {
            if (sr[tid + o] > sr[tid]) sr[tid] = sr[tid + o];
            sd[tid] += sd[tid + o];
            si[tid] += si[tid + o];
        }
        __syncthreads();
    }
    if (tid == 0) { s_bA = sr[0]; s_z2 = sd[0]; s_na = si[0]; }
    __syncthreads();

    const int m2full = s_m2;
    const int m2 = min(m2full, KEYS);
    int msz = 32; while (msz < m2) msz <<= 1;
    for (int i = tid; i < msz; i += T)
        if (i >= m2) keysB[i] = 0xFFFFFFFFFFFFFFFFull;
    __syncthreads();
    if (m2 > 0) {
        for (int kk = 2; kk <= msz; kk <<= 1) {
            for (int jj = kk >> 1; jj > 0; jj >>= 1) {
                for (int i2 = tid; i2 < msz; i2 += T) {
                    int ixj = i2 ^ jj;
                    if (ixj > i2) {
                        ull a = keysB[i2], b = keysB[ixj];
                        bool up = ((i2 & kk) == 0);
                        if ((a > b) == up) { keysB[i2] = b; keysB[ixj] = a; }
                    }
                }
                __syncthreads();
            }
        }
    }
    {
        double loc[8]; double part = 0.0;
        #pragma unroll
        for (int j = 0; j < 8; j++) {
            int idx = tid * 8 + j;
            double ev = (idx < m2)
                ? (double)__uint_as_float(~(unsigned)(keysB[idx] >> 32)) : 0.0;
            part += ev; loc[j] = part;
        }
        sd[tid] = part;
        __syncthreads();
        for (int off = 1; off < T; off <<= 1) {
            double add = (tid >= off) ? sd[tid - off] : 0.0;
            __syncthreads();
            sd[tid] += add;
            __syncthreads();
        }
        const double cum0 = zsure + s_z2;
        double b0 = (tid > 0) ? sd[tid - 1] : 0.0;
        #pragma unroll
        for (int j = 0; j < 8; j++) {
            int idx = tid * 8 + j;
            if (idx < m2 && (cum0 + b0 + loc[j]) <= cd) atomicMax(&s_K, idx);
        }
    }
    __syncthreads();
    int K = s_K;
    if (m2full > KEYS || cnt > CAND) K = m2 - 1;           // overflow fallback
    if (K < 0 && nkept == 0 && s_na == 0 && m2 > 0) K = 0; // rank 0 always kept

    ull b3 = (tid == 0) ? (gbest > s_bA ? gbest : s_bA) : 0ull;
    for (int i = tid; i <= K; i += T) {
        ull key = keysB[i];
        unsigned eb = ~(unsigned)(key >> 32);
        ull pk = race_pack(__uint_as_float(eb), row,
                           (int)(unsigned)(key & 0xFFFFFFFFull));
        if (pk > b3) b3 = pk;
    }
    sr[tid] = b3;
    __syncthreads();
    for (int o = T >> 1; o > 0; o >>= 1) {
        if (tid < o && sr[tid + o] > sr[tid]) sr[tid] = sr[tid + o];
        __syncthreads();
    }
    if (tid == 0) {
        int greedy = g_greedy[row];
        int winner = (sr[0] == 0ull) ? greedy
                                     : (int)(~(unsigned)(sr[0] & 0xFFFFFFFFull));
        float temp = temps[row];
        out[row] = (float)((temp <= 1e-10f) ? greedy : winner);
    }
}

extern "C" void kernel_launch(void* const* d_in, const int* in_sizes, int n_in,
                              void* d_out, int out_size) {
    const float* logits = (const float*)d_in[0];
    const float* temps  = (const float*)d_in[1];
    const float* topps  = (const float*)d_in[2];
    float* out = (float*)d_out;

    kA<<<dim3(CSPLIT, NROWS), T>>>(logits, temps, topps);
    kB<<<dim3(CSPLIT, NROWS), T>>>(logits);
    kC<<<NROWS, T>>>(temps, out);
}

// round 17
// speedup vs baseline: 1.2932x; 1.0779x over previous
#include <cuda_runtime.h>
#include <cuda_bf16.h>
#include <math.h>

#define VOCAB  128000
#define NROWS  256
#define CSPLIT 16
#define SLICE  (VOCAB / CSPLIT)     /* 8000 */
#define S4     (SLICE / 4)          /* 2000 float4 */
#define T      256
#define ITERS  ((S4 + T - 1) / T)   /* 8 */
#define NB1    32                   /* coarse logit bins over [-3, 5] */
#define CAND   16384
#define KEYS   2048
#define BUCK   4096
#define BUFSZ  1024                 /* per-CTA smem candidate buffer */
#define TC     1024                 /* kC block size */

typedef unsigned long long ull;

// ---------------- device-global scratch (static zero-init; self-resetting) ---
__device__ ull    g_pmax[NROWS][CSPLIT];
__device__ float  g_hist32[NROWS][CSPLIT][NB1];
__device__ double g_Zs[NROWS][CSPLIT];
__device__ int    g_tickA[NROWS];
__device__ float  g_invt[NROWS], g_negxm[NROWS];
__device__ int    g_c1[NROWS];
__device__ double g_cd[NROWS];
__device__ int    g_greedy[NROWS];
__device__ double g_zhi[NROWS];
__device__ int    g_nkept[NROWS];
__device__ int    g_cnt[NROWS];
__device__ ull    g_cand[NROWS][CAND];    /* 33.5MB */
__device__ ull    g_best[NROWS];

// ---------------- helpers ----------------------------------------------------
__device__ __forceinline__ float comp_e(float l, float invt, float negxm) {
    return __expf(__fmaf_rn(l, invt, negxm));
}
__device__ __forceinline__ unsigned ordbits(float f) {
    unsigned u = __float_as_uint(f);
    return (u & 0x80000000u) ? ~u : (u | 0x80000000u);
}
__device__ __forceinline__ float unordbits(unsigned u) {
    unsigned b = (u & 0x80000000u) ? (u & 0x7FFFFFFFu) : ~u;
    return __uint_as_float(b);
}
// coarse bin: 32 bins of width 0.25 over l in [-3, 5]; pure function of l
__device__ __forceinline__ int lbin32(float l) {
    int b = __float2int_rd(__fmaf_rn(l, 4.0f, 12.0f));
    return min(NB1 - 1, max(0, b));
}
// JAX threefry2x32, 20 rounds, key = (0, 1)
__device__ __forceinline__ void threefry01(unsigned& x0, unsigned& x1) {
    const unsigned k0 = 0u, k1 = 1u, k2 = 0x1BD11BDAu ^ k0 ^ k1;
    x0 += k0; x1 += k1;
#define TFR(r) { x0 += x1; x1 = __funnelshift_l(x1, x1, (r)); x1 ^= x0; }
    TFR(13) TFR(15) TFR(26) TFR(6)
    x0 += k1; x1 += k2 + 1u;
    TFR(17) TFR(29) TFR(16) TFR(24)
    x0 += k2; x1 += k0 + 2u;
    TFR(13) TFR(15) TFR(26) TFR(6)
    x0 += k0; x1 += k1 + 3u;
    TFR(17) TFR(29) TFR(16) TFR(24)
    x0 += k1; x1 += k2 + 4u;
    TFR(13) TFR(15) TFR(26) TFR(6)
    x0 += k2; x1 += k0 + 5u;
#undef TFR
}
__device__ __forceinline__ ull race_pack(float e, int row, int v) {
    unsigned x0 = 0u;
    unsigned x1 = (unsigned)row * (unsigned)VOCAB + (unsigned)v;
    threefry01(x0, x1);
    unsigned bits = x0 ^ x1;
    float u  = __uint_as_float((bits >> 9) | 0x3F800000u) - 1.0f;
    float nz = fmaxf(-log1pf(-u), 1e-10f);
    float sc = __fdividef(e, nz);
    return ((ull)__float_as_uint(sc) << 32) | (ull)(unsigned)(~(unsigned)v);
}

// =============================================================================
// K_A: max/argmax + Z (Kahan) + conflict-free 32-bin coarse mass histogram;
//      fixed-trip unrolled sweeps (MLP=8); last CTA: rescale/reduce/scan.
// =============================================================================
__global__ __launch_bounds__(T) void kA(const float* __restrict__ logits,
                                        const float* __restrict__ temps,
                                        const float* __restrict__ topps)
{
    __shared__ float  hA[NB1 * 256];    // 32KB: [bin][slot=tid], bank = lane
    __shared__ ull    sr[T];
    __shared__ double sd[T];
    __shared__ double s_scale[CSPLIT];
    __shared__ int    s_last;

    const int row = blockIdx.y, c = blockIdx.x, tid = threadIdx.x;
    const float4* L4 = reinterpret_cast<const float4*>(
        logits + (size_t)row * VOCAB + (size_t)c * SLICE);

    // ---- pass A: slice max + argmax (batched loads) -------------------------
    float bm = -INFINITY; int bi = 0;
    #pragma unroll
    for (int it = 0; it < ITERS; it++) {
        int i = tid + it * T;
        bool v = i < S4;
        float4 qv = v ? L4[i] : make_float4(-INFINITY, -INFINITY, -INFINITY, -INFINITY);
        int b = c * SLICE + 4 * i;
        if (qv.x > bm) { bm = qv.x; bi = b; }
        if (qv.y > bm) { bm = qv.y; bi = b + 1; }
        if (qv.z > bm) { bm = qv.z; bi = b + 2; }
        if (qv.w > bm) { bm = qv.w; bi = b + 3; }
    }
    sr[tid] = ((ull)ordbits(bm) << 32) | (ull)(unsigned)(~(unsigned)bi);
    __syncthreads();
    for (int o = T >> 1; o > 0; o >>= 1) {
        if (tid < o && sr[tid + o] > sr[tid]) sr[tid] = sr[tid + o];
        __syncthreads();
    }
    const ull pm = sr[0];
    if (tid == 0) g_pmax[row][c] = pm;

    for (int i = tid; i < NB1 * 256; i += T) hA[i] = 0.0f;
    __syncthreads();

    const float temp  = temps[row];
    const float t     = fmaxf(temp, 1e-5f);
    const float invt  = __frcp_rn(t);
    const float mc    = unordbits((unsigned)(pm >> 32));
    const float negxc = -__fmul_rn(mc, invt);

    // ---- pass B: Z (Kahan) + conflict-free coarse hist (batched loads) -----
    float zs = 0.0f, zc = 0.0f;
    #pragma unroll
    for (int it = 0; it < ITERS; it++) {
        int i = tid + it * T;
        bool v = i < S4;
        float4 qv = v ? L4[i] : make_float4(-1e30f, -1e30f, -1e30f, -1e30f);
        float ls[4] = { qv.x, qv.y, qv.z, qv.w };
        #pragma unroll
        for (int j = 0; j < 4; j++) {
            float l = ls[j];
            float e = comp_e(l, invt, negxc);   // 0 for sentinel
            float y = e - zc; float t2 = zs + y; zc = (t2 - zs) - y; zs = t2;
            if (v) hA[(lbin32(l) << 8) + tid] += e;
        }
    }
    sd[tid] = (double)zs - (double)zc;
    __syncthreads();
    for (int o = T >> 1; o > 0; o >>= 1) {
        if (tid < o) sd[tid] += sd[tid + o];
        __syncthreads();
    }
    if (tid == 0) g_Zs[row][c] = sd[0];
    if (tid < NB1 * 8) {
        int b = tid >> 3, s0 = (tid & 7) << 5;
        float v = 0.0f;
        #pragma unroll
        for (int s = 0; s < 32; s++) v += hA[(b << 8) + s0 + s];
        hA[(b << 8) + s0] = v;
    }
    __syncthreads();
    if (tid < NB1) {
        float v = 0.0f;
        #pragma unroll
        for (int s = 0; s < 8; s++) v += hA[(tid << 8) + (s << 5)];
        g_hist32[row][c][tid] = v;
    }
    __threadfence();
    __syncthreads();
    if (tid == 0) s_last = (atomicAdd(&g_tickA[row], 1) == CSPLIT - 1);
    __syncthreads();
    if (!s_last) return;
    __threadfence();

    if (tid == 0) g_tickA[row] = 0;
    ull k = g_pmax[row][0];
    #pragma unroll
    for (int j = 1; j < CSPLIT; j++) { ull o = g_pmax[row][j]; if (o > k) k = o; }
    const float m = unordbits((unsigned)(k >> 32));
    if (tid < CSPLIT) {
        float mcj = unordbits((unsigned)(g_pmax[row][tid] >> 32));
        s_scale[tid] = exp(((double)mcj - (double)m) * (double)invt);
    }
    __syncthreads();
    if (tid < NB1) {
        double v = 0.0;
        #pragma unroll
        for (int cs = 0; cs < CSPLIT; cs++)
            v += s_scale[cs] * (double)g_hist32[row][cs][tid];
        sd[tid] = v;
    }
    __syncthreads();
    if (tid == 0) {
        double Z = 0.0;
        #pragma unroll
        for (int cs = 0; cs < CSPLIT; cs++) Z += s_scale[cs] * g_Zs[row][cs];
        double cd = (double)topps[row] * Z;
        double cum = 0.0; int c1 = 0;
        for (int b = NB1 - 1; b >= 0; b--) {
            cum += sd[b];
            if (cum > cd) { c1 = b; break; }
        }
        g_c1[row]    = c1;
        g_cd[row]    = cd;
        g_invt[row]  = invt;
        g_negxm[row] = -__fmul_rn(m, invt);
        g_greedy[row] = (int)(~(unsigned)(k & 0xFFFFFFFFull));
        g_cnt[row] = 0; g_best[row] = 0ull; g_zhi[row] = 0.0; g_nkept[row] = 0;
    }
}

// =============================================================================
// K_B: bin-compare classification, warp-compacted race (exp in drain),
//      buffered candidate gather (smem buffer + one flush per CTA).
// =============================================================================
__global__ __launch_bounds__(T) void kB(const float* __restrict__ logits)
{
    __shared__ ull    buf[BUFSZ];      // 8KB candidate buffer
    __shared__ ull    sr[T];
    __shared__ double sd[T];
    __shared__ int    si[T];
    __shared__ uint2  q[8][64];        // 4KB per-warp kept-token queues
    __shared__ int    s_bn, s_base;

    const int row = blockIdx.y, c = blockIdx.x, tid = threadIdx.x;
    const int wid = tid >> 5, lane = tid & 31;
    const unsigned lmlt = (1u << lane) - 1u;
    const int   c1 = g_c1[row];
    const float invt = g_invt[row], negxm = g_negxm[row];
    const float4* L4 = reinterpret_cast<const float4*>(
        logits + (size_t)row * VOCAB + (size_t)c * SLICE);

    if (tid == 0) s_bn = 0;
    __syncthreads();

    ull best = 0ull; float zs = 0.0f, zc = 0.0f; int qn = 0, nk = 0;
    #pragma unroll 2
    for (int it = 0; it < ITERS; it++) {
        int i = tid + it * T;
        bool valid = i < S4;
        float4 qv = valid ? L4[i] : make_float4(-1e30f, -1e30f, -1e30f, -1e30f);
        float ls[4] = { qv.x, qv.y, qv.z, qv.w };
        int vb = c * SLICE + 4 * i;
        #pragma unroll
        for (int j = 0; j < 4; j++) {
            float l = ls[j];
            int b = lbin32(l);
            bool kept = valid && (b > c1);
            unsigned bal = __ballot_sync(0xFFFFFFFFu, kept);
            if (kept) {
                int pos = qn + __popc(bal & lmlt);
                q[wid][pos] = make_uint2(__float_as_uint(l), (unsigned)(vb + j));
            }
            qn += __popc(bal); nk += __popc(bal);
            if (qn >= 32) {                 // warp-uniform
                qn -= 32;
                uint2 en = q[wid][qn + lane];
                float e = comp_e(__uint_as_float(en.x), invt, negxm);
                float y = e - zc; float t2 = zs + y; zc = (t2 - zs) - y; zs = t2;
                ull pk = race_pack(e, row, (int)en.y);
                if (pk > best) best = pk;
            }
            bool cnd = valid && (b == c1);
            ull key = 0ull;
            if (cnd) {
                float e = comp_e(l, invt, negxm);
                unsigned eb = __float_as_uint(e);
                if (eb == 0u) cnd = false;
                else key = ((ull)(~eb) << 32) | (ull)(unsigned)(vb + j);
            }
            unsigned calb = __ballot_sync(0xFFFFFFFFu, cnd);
            if (calb) {
                int leader = __ffs(calb) - 1;
                int base = 0;
                if (lane == leader) base = atomicAdd(&s_bn, __popc(calb));
                base = __shfl_sync(0xFFFFFFFFu, base, leader);
                if (cnd) {
                    int p = base + __popc(calb & lmlt);
                    if (p < BUFSZ) buf[p] = key;
                    else {                       // rare spill
                        int gp = atomicAdd(&g_cnt[row], 1);
                        if (gp < CAND) g_cand[row][gp] = key;
                    }
                }
            }
        }
    }
    if (lane < qn) {                        // drain leftovers
        uint2 en = q[wid][lane];
        float e = comp_e(__uint_as_float(en.x), invt, negxm);
        float y = e - zc; float t2 = zs + y; zc = (t2 - zs) - y; zs = t2;
        ull pk = race_pack(e, row, (int)en.y);
        if (pk > best) best = pk;
    }
    sr[tid] = best;
    sd[tid] = (double)zs - (double)zc;
    si[tid] = (lane == 0) ? nk : 0;         // nk warp-uniform
    __syncthreads();
    for (int o = T >> 1; o > 0; o >>= 1) {
        if (tid < o) {
            if (sr[tid + o] > sr[tid]) sr[tid] = sr[tid + o];
            sd[tid] += sd[tid + o];
            si[tid] += si[tid + o];
        }
        __syncthreads();
    }
    const int bn = min(s_bn, BUFSZ);
    if (tid == 0) {
        s_base = (bn > 0) ? atomicAdd(&g_cnt[row], bn) : 0;
        if (sr[0]) atomicMax(&g_best[row], sr[0]);
        atomicAdd(&g_zhi[row], sd[0]);
        atomicAdd(&g_nkept[row], si[0]);
    }
    __syncthreads();
    const int base = s_base;
    for (int i = tid; i < bn; i += T) {
        int p = base + i;
        if (p < CAND) g_cand[row][p] = buf[i];
    }
}

// =============================================================================
// K_C: per-row exact mini-pipeline over <=16K candidates -> out[row].
// T = 1024 for latency hiding at grid = 256.
// =============================================================================
__global__ __launch_bounds__(TC) void kC(const float* __restrict__ temps,
                                         float* __restrict__ out)
{
    __shared__ ull    s_un[KEYS];      // 16KB; aliased as float bmass[BUCK]
    __shared__ ull    sr[TC];          // 8KB
    __shared__ double sd[TC];          // 8KB
    __shared__ int    si[TC];          // 4KB
    __shared__ int    s_r2, s_m2, s_K;
    __shared__ double s_z2;
    __shared__ int    s_na;
    __shared__ ull    s_bA;

    float* bmass = reinterpret_cast<float*>(s_un);
    ull*   keysB = s_un;

    const int row = blockIdx.x, tid = threadIdx.x;
    if (tid == 0) { s_r2 = 0x7FFFFFFF; s_m2 = 0; s_K = -1; }
    const int    cnt   = g_cnt[row];
    const int    n     = min(cnt, CAND);
    const double cd    = g_cd[row];
    const double zsure = g_zhi[row];
    const int    nkept = g_nkept[row];
    const ull    gbest = g_best[row];

    for (int i = tid; i < BUCK; i += TC) bmass[i] = 0.0f;
    __syncthreads();
    for (int i = tid; i < n; i += TC) {
        unsigned eb = ~(unsigned)(g_cand[row][i] >> 32);
        atomicAdd(&bmass[eb >> 18], __uint_as_float(eb));
    }
    __syncthreads();
    {
        double loc[BUCK / TC]; double part = 0.0;
        #pragma unroll
        for (int j = 0; j < BUCK / TC; j++) {
            int r = tid * (BUCK / TC) + j;
            part += (double)bmass[BUCK - 1 - r];
            loc[j] = part;
        }
        sd[tid] = part;
        __syncthreads();
        for (int off = 1; off < TC; off <<= 1) {
            double add = (tid >= off) ? sd[tid - off] : 0.0;
            __syncthreads();
            sd[tid] += add;
            __syncthreads();
        }
        const double budget = cd - zsure;
        double b0 = (tid > 0) ? sd[tid - 1] : 0.0;
        #pragma unroll
        for (int j = 0; j < BUCK / TC; j++) {
            if (b0 + loc[j] > budget) {
                atomicMin(&s_r2, tid * (BUCK / TC) + j);
                break;
            }
        }
    }
    __syncthreads();
    const int b2 = (s_r2 == 0x7FFFFFFF) ? -1 : (BUCK - 1 - s_r2);
    __syncthreads();          // bmass reads done; keysB reuse safe after this

    double z2 = 0.0; int na = 0; ull bA = 0ull;
    for (int i = tid; i < n; i += TC) {
        ull key = g_cand[row][i];
        unsigned eb = ~(unsigned)(key >> 32);
        int bu = (int)(eb >> 18);
        if (bu > b2) {
            z2 += (double)__uint_as_float(eb);
            na++;
            ull pk = race_pack(__uint_as_float(eb), row,
                               (int)(unsigned)(key & 0xFFFFFFFFull));
            if (pk > bA) bA = pk;
        } else if (bu == b2) {
            int p = atomicAdd(&s_m2, 1);
            if (p < KEYS) keysB[p] = key;
        }
    }
    sr[tid] = bA; sd[tid] = z2; si[tid] = na;
    __syncthreads();
    for (int o = TC >> 1; o > 0; o >>= 1) {
        if (tid < o) {
            if (sr[tid + o] > sr[tid]) sr[tid] = sr[tid + o];
            sd[tid] += sd[tid + o];
            si[tid] += si[tid + o];
        }
        __syncthreads();
    }
    if (tid == 0) { s_bA = sr[0]; s_z2 = sd[0]; s_na = si[0]; }
    __syncthreads();

    const int m2full = s_m2;
    const int m2 = min(m2full, KEYS);
    int msz = 32; while (msz < m2) msz <<= 1;
    for (int i = tid; i < msz; i += TC)
        if (i >= m2) keysB[i] = 0xFFFFFFFFFFFFFFFFull;
    __syncthreads();
    if (m2 > 0) {
        for (int kk = 2; kk <= msz; kk <<= 1) {
            for (int jj = kk >> 1; jj > 0; jj >>= 1) {
                for (int i2 = tid; i2 < msz; i2 += TC) {
                    int ixj = i2 ^ jj;
                    if (ixj > i2) {
                        ull a = keysB[i2], b = keysB[ixj];
                        bool up = ((i2 & kk) == 0);
                        if ((a > b) == up) { keysB[i2] = b; keysB[ixj] = a; }
                    }
                }
                __syncthreads();
            }
        }
    }
    {
        double loc[KEYS / TC]; double part = 0.0;
        #pragma unroll
        for (int j = 0; j < KEYS / TC; j++) {
            int idx = tid * (KEYS / TC) + j;
            double ev = (idx < m2)
                ? (double)__uint_as_float(~(unsigned)(keysB[idx] >> 32)) : 0.0;
            part += ev; loc[j] = part;
        }
        sd[tid] = part;
        __syncthreads();
        for (int off = 1; off < TC; off <<= 1) {
            double add = (tid >= off) ? sd[tid - off] : 0.0;
            __syncthreads();
            sd[tid] += add;
            __syncthreads();
        }
        const double cum0 = zsure + s_z2;
        double b0 = (tid > 0) ? sd[tid - 1] : 0.0;
        #pragma unroll
        for (int j = 0; j < KEYS / TC; j++) {
            int idx = tid * (KEYS / TC) + j;
            if (idx < m2 && (cum0 + b0 + loc[j]) <= cd) atomicMax(&s_K, idx);
        }
    }
    __syncthreads();
    int K = s_K;
    if (m2full > KEYS || cnt > CAND) K = m2 - 1;           // overflow fallback
    if (K < 0 && nkept == 0 && s_na == 0 && m2 > 0) K = 0; // rank 0 always kept

    ull b3 = (tid == 0) ? (gbest > s_bA ? gbest : s_bA) : 0ull;
    for (int i = tid; i <= K; i += TC) {
        ull key = keysB[i];
        unsigned eb = ~(unsigned)(key >> 32);
        ull pk = race_pack(__uint_as_float(eb), row,
                           (int)(unsigned)(key & 0xFFFFFFFFull));
        if (pk > b3) b3 = pk;
    }
    sr[tid] = b3;
    __syncthreads();
    for (int o = TC >> 1; o > 0; o >>= 1) {
        if (tid < o && sr[tid + o] > sr[tid]) sr[tid] = sr[tid + o];
        __syncthreads();
    }
    if (tid == 0) {
        int greedy = g_greedy[row];
        int winner = (sr[0] == 0ull) ? greedy
                                     : (int)(~(unsigned)(sr[0] & 0xFFFFFFFFull));
        float temp = temps[row];
        out[row] = (float)((temp <= 1e-10f) ? greedy : winner);
    }
}

extern "C" void kernel_launch(void* const* d_in, const int* in_sizes, int n_in,
                              void* d_out, int out_size) {
    const float* logits = (const float*)d_in[0];
    const float* temps  = (const float*)d_in[1];
    const float* topps  = (const float*)d_in[2];
    float* out = (float*)d_out;

    kA<<<dim3(CSPLIT, NROWS), T>>>(logits, temps, topps);
    kB<<<dim3(CSPLIT, NROWS), T>>>(logits);
    kC<<<NROWS, TC>>>(temps, out);
}